// round 14
// baseline (speedup 1.0000x reference)
#include <cuda_runtime.h>
#include <cuda_bf16.h>

// ---------------------------------------------------------------------------
// Net_80796924772492: small permuted-group CNN, B=64.
// front(dw1+pc1+relu+pool + init tail) -> dw2 -> pc2(+relu+pool, ldg weights)
//  -> oo 1x1 515->100 split-K partials -> fc1(fused relu-combine) -> fc2+fc3
// ---------------------------------------------------------------------------

#define BATCH 64

__device__ float g_buf2[BATCH * 51 * 14 * 14];   // front out
__device__ float g_buf3p[BATCH * 26000];         // dw2 out, [b][py5][260ch][20]
__device__ float g_buf4t[BATCH * 13100];         // pc2 out, [b][25 px][524 c]
__device__ float g_buf5[BATCH * 2500];           // oo partial (K-half 0, +bias)
__device__ float g_buf5b[BATCH * 2500];          // oo partial (K-half 1)
__device__ float g_buf6[BATCH * 120];            // fc1 out

// pc1 per-group info: (j, rep = i*ncpf+j, base = k*ncpf, 0)
__device__ int4 g_g1info[51];
// pc2 groups sorted by k, quads of 4 share k: slot -> (g, j, rep, base=k*51)
__device__ int4 g_g2sorted[524];
// pre-padded pc2 weights: [slot 524][52] (zero pad c=51, dup pad slots)
__device__ float g_w2pad[524 * 52];
// TRANSPOSED padded oo weights: [520 c][104 oc] (zero pads)
__device__ float g_oowT[520 * 104];

// ---------------------------------------------------------------------------
__device__ __forceinline__ int4 group_info1(int g) {   // F=6, ncpf=3
    int rem = g, i = 0;
    for (;;) {
        int cnt = (6 - i) + 2 * (5 - i);
        if (rem < cnt) break;
        rem -= cnt; i++;
    }
    int j, k;
    if (rem < 6 - i) { j = 0; k = i + rem; }
    else { rem -= (6 - i); j = 1 + rem / (5 - i); k = i + 1 + rem % (5 - i); }
    int4 r; r.x = j; r.y = i * 3 + j; r.z = k * 3; r.w = 0;
    return r;
}

__device__ __forceinline__ int4 slot_info2(int s) {
    const int qs[6] = {0, 1, 14, 40, 79, 131};
    const int Gk[5] = {1, 52, 103, 154, 205};
    int q = s >> 2;
    int k = 0;
    while (k < 4 && q >= qs[k + 1]) k++;
    int r = s - qs[k] * 4;
    if (r > Gk[k] - 1) r = Gk[k] - 1;       // pad: replicate last group
    int i, j;
    if (r <= k) { i = r; j = 0; }
    else { int r2 = r - (k + 1); i = r2 / 50; j = 1 + r2 % 50; }
    int base_i = 205 * i - 51 * (i * (i - 1) / 2);
    int off = (j == 0) ? (k - i) : (5 - i) + (j - 1) * (4 - i) + (k - i - 1);
    int4 v; v.x = base_i + off; v.y = j; v.z = i * 51 + j; v.w = k * 51;
    return v;
}

// init work: tables + padded weights + static pad zeroing (grid-stride).
__device__ void init_work(int ib, int tid,
                          const float* __restrict__ pc2_w,
                          const float* __restrict__ oo_w) {
    const int CA = 51, CB = 524, CC = 524 * 52, CD = 520 * 104;
    const int CE = 64 * 225;   // g_buf4t pads: 25 px * 9 c
    const int CF = 64 * 500;   // g_buf3p pads: 5 py * 100
    int total = CA + CB + CC + CD + CE + CF;
    for (int t = ib * 256 + tid; t < total; t += 64 * 256) {
        int i = t;
        if (i < CA) { g_g1info[i] = group_info1(i); continue; }
        i -= CA;
        if (i < CB) { g_g2sorted[i] = slot_info2(i); continue; }
        i -= CB;
        if (i < CC) {
            int s = i / 52, c = i % 52;
            int g = slot_info2(s).x;
            g_w2pad[i] = (c < 51) ? __ldg(pc2_w + g * 51 + c) : 0.f;
            continue;
        }
        i -= CC;
        if (i < CD) {
            int c = i / 104, r = i % 104;   // transposed: [c][oc]
            g_oowT[i] = (r < 100 && c < 515) ? __ldg(oo_w + r * 515 + c) : 0.f;
            continue;
        }
        i -= CD;
        if (i < CE) {
            int b = i / 225, r = i % 225;
            int px = r / 9, c = 515 + r % 9;
            g_buf4t[b * 13100 + px * 524 + c] = 0.f;
            continue;
        }
        i -= CE;
        {
            int b = i / 500, r = i % 500;
            int py = r / 100, q = r % 100;
            g_buf3p[b * 26000 + py * 5200 + 5100 + q] = 0.f;
        }
    }
}

// ---------------------------------------------------------------------------
// front: dw1 + pc1 + relu + pool. Blocks 0..447 = (b, row-slice h of 7).
// Blocks 448..511 run init_work.
// ---------------------------------------------------------------------------
__global__ void front_kernel(const float* __restrict__ x,
                             const float* __restrict__ dw1_w,
                             const float* __restrict__ dw1_b,
                             const float* __restrict__ pc1_w,
                             const float* __restrict__ pc1_b,
                             const float* __restrict__ pc2_w,
                             const float* __restrict__ oo_w) {
    __shared__ float sx[3 * 264];    // [ch][8 rows][pitch 33]
    __shared__ float sd[18 * 113];   // [oc][4 rows][28], pitch 113
    __shared__ float sw1[153];
    __shared__ float sb1[51];
    int tid = threadIdx.x;
    if (blockIdx.x >= 448) {
        init_work(blockIdx.x - 448, tid, pc2_w, oo_w);
        return;
    }
    int b = blockIdx.x / 7, h = blockIdx.x % 7;
    int r0 = 4 * h;

    for (int i = tid; i < 768; i += 256) {
        int ch = i >> 8, t = i & 255;
        int rr = t >> 5, c = t & 31;
        sx[ch * 264 + rr * 33 + c] = x[(b * 3 + ch) * 1024 + (r0 + rr) * 32 + c];
    }
    if (tid < 153) sw1[tid] = __ldg(pc1_w + tid);
    if (tid >= 160 && tid < 211) sb1[tid - 160] = __ldg(pc1_b + tid - 160);
    __syncthreads();

    // dw1: 18 oc x 4 rows x 2 halves = 144 units (14-wide strips)
    if (tid < 144) {
        int xh = tid & 1;
        int t = tid >> 1;
        int row = t & 3, oc = t >> 2;
        int ci = oc / 6;
        const float* wp = dw1_w + oc * 25;
        float bb = __ldg(dw1_b + oc);
        float acc[14];
#pragma unroll
        for (int q = 0; q < 14; q++) acc[q] = bb;
        for (int ky = 0; ky < 5; ky++) {
            int rb = ci * 264 + (row + ky) * 33 + xh * 14;
            float r[18];
#pragma unroll
            for (int q = 0; q < 18; q++) r[q] = sx[rb + q];
#pragma unroll
            for (int kx = 0; kx < 5; kx++) {
                float ww = __ldg(wp + ky * 5 + kx);
#pragma unroll
                for (int xo = 0; xo < 14; xo++)
                    acc[xo] = fmaf(r[xo + kx], ww, acc[xo]);
            }
        }
        float* dst = sd + oc * 113 + row * 28 + xh * 14;
#pragma unroll
        for (int q = 0; q < 14; q++) dst[q] = acc[q];
    }
    __syncthreads();

    // pc1 + relu + pool: 51 g x 2 pooled rows x 14 px = 1428 units
    for (int u = tid; u < 1428; u += 256) {
        int px = u % 14;
        int t = u / 14;
        int pyl = t & 1, g = t >> 1;
        int4 gi = g_g1info[g];
        int ch0 = (gi.x == 0) ? gi.y : gi.z + 0;
        int ch1 = (gi.x == 1) ? gi.y : gi.z + 1;
        int ch2 = (gi.x == 2) ? gi.y : gi.z + 2;
        const float* p0 = sd + ch0 * 113;
        const float* p1 = sd + ch1 * 113;
        const float* p2 = sd + ch2 * 113;
        float w0 = sw1[g * 3 + 0], w1 = sw1[g * 3 + 1], w2 = sw1[g * 3 + 2];
        float bb = sb1[g];
        float m = 0.0f;
#pragma unroll
        for (int dy = 0; dy < 2; dy++) {
#pragma unroll
            for (int dx = 0; dx < 2; dx++) {
                int off = (2 * pyl + dy) * 28 + 2 * px + dx;
                float v = bb;
                v = fmaf(w0, p0[off], v);
                v = fmaf(w1, p1[off], v);
                v = fmaf(w2, p2[off], v);
                m = fmaxf(m, v);
            }
        }
        g_buf2[((b * 51 + g) * 14 + 2 * h + pyl) * 14 + px] = m;
    }
}

// ---------------------------------------------------------------------------
// dw2: [64,51,14,14] -> [b][py][260ch][20]. Block=(b, 4-ch chunk)x13.
// ---------------------------------------------------------------------------
__global__ void dw2_kernel(const float* __restrict__ w,
                           const float* __restrict__ bias) {
    __shared__ float s[4 * 200];
    int b = blockIdx.x / 13, chunk = blockIdx.x % 13;
    int c0 = chunk * 4;
    int nch = (chunk == 12) ? 3 : 4;
    int tid = threadIdx.x;
    const float* src = g_buf2 + (b * 51 + c0) * 196;
    int n = nch * 196;
    for (int i = tid; i < n; i += 256)
        s[(i / 196) * 200 + i % 196] = src[i];
    __syncthreads();

    int nu = nch * 50;
    if (tid < nu) {
        int ol = tid / 10, yo = tid % 10;
        int o = c0 * 5 + ol;
        int cil = ol / 5;
        const float* wp = w + o * 25;
        float bb = __ldg(bias + o);
        float acc[10];
#pragma unroll
        for (int t = 0; t < 10; t++) acc[t] = bb;
        for (int ky = 0; ky < 5; ky++) {
            int rb = cil * 200 + (yo + ky) * 14;
            float r[14];
#pragma unroll
            for (int t = 0; t < 14; t++) r[t] = s[rb + t];
#pragma unroll
            for (int kx = 0; kx < 5; kx++) {
                float ww = __ldg(wp + ky * 5 + kx);
#pragma unroll
                for (int xo = 0; xo < 10; xo++)
                    acc[xo] = fmaf(r[xo + kx], ww, acc[xo]);
            }
        }
        float* dst = g_buf3p + b * 26000 + (yo >> 1) * 5200 + o * 20 +
                     (yo & 1) * 10;
#pragma unroll
        for (int t = 0; t < 10; t++) dst[t] = acc[t];
    }
}

// ---------------------------------------------------------------------------
// pc2 + relu + pool:
//   out[g] = dot51(w[g], x[k-block]) + w[g,j]*(x[rep] - x[base+j])
// Thread = (quad, pooled px). Block = (b, py, third). Inputs in 20KB smem;
// weights read directly from L1-resident g_w2pad via __ldg.
// ---------------------------------------------------------------------------
__global__ __launch_bounds__(256, 4)
void pc2pool_kernel(const float* __restrict__ bias) {
    __shared__ float s_in[5120];     // 256 ch x 20
    int bid = blockIdx.x;
    int b = bid / 15;
    int t = bid % 15;
    int py = t / 3, part = t % 3;
    int q0 = part * 44;
    int nq = (part == 2) ? 43 : 44;
    int tid = threadIdx.x;

    {
        float4* si4 = (float4*)s_in;
        const float4* g4 = (const float4*)(g_buf3p + b * 26000 + py * 5200);
        for (int i = tid; i < 1280; i += 256) si4[i] = g4[i];
    }
    __syncthreads();

    int u = tid;
    if (u < nq * 5) {
        int ql = u / 5, px = u % 5;
        int slot0 = (q0 + ql) * 4;
        int base = g_g2sorted[slot0].w;
        const float4* wg = (const float4*)g_w2pad + slot0 * 13;
        float a[4][4];
#pragma unroll
        for (int s2 = 0; s2 < 4; s2++)
#pragma unroll
            for (int p = 0; p < 4; p++) a[s2][p] = 0.f;
        int xb = base * 20 + 2 * px;
#pragma unroll 2
        for (int cc4 = 0; cc4 < 13; cc4++) {
            float4 w0 = __ldg(wg + cc4);
            float4 w1 = __ldg(wg + 13 + cc4);
            float4 w2 = __ldg(wg + 26 + cc4);
            float4 w3 = __ldg(wg + 39 + cc4);
            float w0a[4] = {w0.x, w0.y, w0.z, w0.w};
            float w1a[4] = {w1.x, w1.y, w1.z, w1.w};
            float w2a[4] = {w2.x, w2.y, w2.z, w2.w};
            float w3a[4] = {w3.x, w3.y, w3.z, w3.w};
#pragma unroll
            for (int t2 = 0; t2 < 4; t2++) {
                int c = cc4 * 4 + t2;
                float2 top = *(const float2*)&s_in[xb + c * 20];
                float2 bot = *(const float2*)&s_in[xb + c * 20 + 10];
                a[0][0] = fmaf(w0a[t2], top.x, a[0][0]);
                a[0][1] = fmaf(w0a[t2], top.y, a[0][1]);
                a[0][2] = fmaf(w0a[t2], bot.x, a[0][2]);
                a[0][3] = fmaf(w0a[t2], bot.y, a[0][3]);
                a[1][0] = fmaf(w1a[t2], top.x, a[1][0]);
                a[1][1] = fmaf(w1a[t2], top.y, a[1][1]);
                a[1][2] = fmaf(w1a[t2], bot.x, a[1][2]);
                a[1][3] = fmaf(w1a[t2], bot.y, a[1][3]);
                a[2][0] = fmaf(w2a[t2], top.x, a[2][0]);
                a[2][1] = fmaf(w2a[t2], top.y, a[2][1]);
                a[2][2] = fmaf(w2a[t2], bot.x, a[2][2]);
                a[2][3] = fmaf(w2a[t2], bot.y, a[2][3]);
                a[3][0] = fmaf(w3a[t2], top.x, a[3][0]);
                a[3][1] = fmaf(w3a[t2], top.y, a[3][1]);
                a[3][2] = fmaf(w3a[t2], bot.x, a[3][2]);
                a[3][3] = fmaf(w3a[t2], bot.y, a[3][3]);
            }
        }
#pragma unroll
        for (int s2 = 0; s2 < 4; s2++) {
            int4 gi = g_g2sorted[slot0 + s2];
            float wj = __ldg(&g_w2pad[(slot0 + s2) * 52 + gi.y]);
            int rb2 = gi.z * 20 + 2 * px;
            int bb2 = (base + gi.y) * 20 + 2 * px;
            float2 rt = *(const float2*)&s_in[rb2];
            float2 rb_ = *(const float2*)&s_in[rb2 + 10];
            float2 bt = *(const float2*)&s_in[bb2];
            float2 bb_ = *(const float2*)&s_in[bb2 + 10];
            float v0 = fmaf(wj, rt.x - bt.x, a[s2][0]);
            float v1 = fmaf(wj, rt.y - bt.y, a[s2][1]);
            float v2 = fmaf(wj, rb_.x - bb_.x, a[s2][2]);
            float v3 = fmaf(wj, rb_.y - bb_.y, a[s2][3]);
            float m = fmaxf(fmaxf(v0, v1), fmaxf(v2, v3)) + __ldg(bias + gi.x);
            g_buf4t[b * 13100 + (py * 5 + px) * 524 + gi.x] = fmaxf(m, 0.f);
        }
    }
}

// ---------------------------------------------------------------------------
// oo split-K: 1x1 conv 515->100, partial sums over 260-channel halves.
// Block = (b, px-group of 5, K-half) -> grid 640. x half-tile [5][260] in
// 5.2KB smem; weights coalesced float2 __ldg from g_oowT (warp = 32
// consecutive oc-pairs; all lanes same px row -> x LDS broadcast).
// Half 0 adds bias; relu happens in fc1 after combine.
// ---------------------------------------------------------------------------
__global__ __launch_bounds__(256, 6)
void oo_kernel(const float* __restrict__ bias) {
    __shared__ float xs[5 * 260];    // 5200 B
    int u = blockIdx.x;
    int b = u / 10;
    int r = u % 10;
    int pg = r >> 1, kh = r & 1;
    int c0 = kh * 260;
    int tid = threadIdx.x;

    {   // stage 5 rows x 65 float4 from g_buf4t[b][pg*5+pxl][c0..c0+260)
        float4* xs4 = (float4*)xs;
        const float* src = g_buf4t + b * 13100 + pg * 5 * 524 + c0;
        for (int i = tid; i < 325; i += 256) {
            int row = i / 65, col = i % 65;
            xs4[row * 65 + col] = *(const float4*)(src + row * 524 + col * 4);
        }
    }
    __syncthreads();

    if (tid < 250) {
        int ocp = tid % 50, pxl = tid / 50;   // warp: consecutive ocp
        int oc = ocp * 2;
        const float2* wT2 = (const float2*)g_oowT + c0 * 52;
        const float* xrow = xs + pxl * 260;
        float a0 = 0.f, a1 = 0.f;
#pragma unroll 4
        for (int cc = 0; cc < 260; cc += 4) {
            float4 xv = *(const float4*)&xrow[cc];
            float2 w0 = __ldg(wT2 + (cc + 0) * 52 + ocp);
            float2 w1 = __ldg(wT2 + (cc + 1) * 52 + ocp);
            float2 w2 = __ldg(wT2 + (cc + 2) * 52 + ocp);
            float2 w3 = __ldg(wT2 + (cc + 3) * 52 + ocp);
            a0 = fmaf(w0.x, xv.x, a0);
            a1 = fmaf(w0.y, xv.x, a1);
            a0 = fmaf(w1.x, xv.y, a0);
            a1 = fmaf(w1.y, xv.y, a1);
            a0 = fmaf(w2.x, xv.z, a0);
            a1 = fmaf(w2.y, xv.z, a1);
            a0 = fmaf(w3.x, xv.w, a0);
            a1 = fmaf(w3.y, xv.w, a1);
        }
        int pix = pg * 5 + pxl;
        float* dst = (kh ? g_buf5b : g_buf5) + b * 2500;
        if (!kh) {
            a0 += __ldg(bias + oc);
            a1 += __ldg(bias + oc + 1);
        }
        dst[oc * 25 + pix] = a0;
        dst[(oc + 1) * 25 + pix] = a1;
    }
}

// ---------------------------------------------------------------------------
// fc1: x = relu(p0 + p1) fused on load; [64,2500] x [120,2500]^T + bias,
// relu. Warp tile = 4 outputs x 4 batch.
// ---------------------------------------------------------------------------
__global__ void fc1_kernel(const float* __restrict__ w,
                           const float* __restrict__ bias) {
    int wid = (blockIdx.x * blockDim.x + threadIdx.x) >> 5;
    int lane = threadIdx.x & 31;
    if (wid >= 480) return;
    int o0 = (wid / 16) * 4;
    int b0 = (wid % 16) * 4;
    const float4* w4 = (const float4*)w;
    const float4* xa = (const float4*)g_buf5;
    const float4* xb = (const float4*)g_buf5b;
    float a[16];
#pragma unroll
    for (int t = 0; t < 16; t++) a[t] = 0.f;
    for (int i = lane; i < 625; i += 32) {
        float4 wv[4], xv[4];
#pragma unroll
        for (int t = 0; t < 4; t++) wv[t] = __ldg(w4 + (o0 + t) * 625 + i);
#pragma unroll
        for (int t = 0; t < 4; t++) {
            float4 pa = xa[(b0 + t) * 625 + i];
            float4 pb = xb[(b0 + t) * 625 + i];
            xv[t].x = fmaxf(pa.x + pb.x, 0.f);
            xv[t].y = fmaxf(pa.y + pb.y, 0.f);
            xv[t].z = fmaxf(pa.z + pb.z, 0.f);
            xv[t].w = fmaxf(pa.w + pb.w, 0.f);
        }
#pragma unroll
        for (int oi = 0; oi < 4; oi++)
#pragma unroll
            for (int bi = 0; bi < 4; bi++) {
                a[oi * 4 + bi] = fmaf(wv[oi].x, xv[bi].x, a[oi * 4 + bi]);
                a[oi * 4 + bi] = fmaf(wv[oi].y, xv[bi].y, a[oi * 4 + bi]);
                a[oi * 4 + bi] = fmaf(wv[oi].z, xv[bi].z, a[oi * 4 + bi]);
                a[oi * 4 + bi] = fmaf(wv[oi].w, xv[bi].w, a[oi * 4 + bi]);
            }
    }
#pragma unroll
    for (int off = 16; off; off >>= 1)
#pragma unroll
        for (int t = 0; t < 16; t++)
            a[t] += __shfl_xor_sync(0xffffffffu, a[t], off);
    if (lane < 16) {
        int oi = lane >> 2, bi = lane & 3;
        g_buf6[(b0 + bi) * 120 + o0 + oi] =
            fmaxf(a[lane] + __ldg(bias + o0 + oi), 0.f);
    }
}

// ---------------------------------------------------------------------------
// fc2 (relu) + fc3 fused. block per batch element.
// ---------------------------------------------------------------------------
__global__ void fc_tail_kernel(const float* __restrict__ w2,
                               const float* __restrict__ b2,
                               const float* __restrict__ w3,
                               const float* __restrict__ b3,
                               float* __restrict__ out) {
    __shared__ float h1[120];
    __shared__ float h2[84];
    int b = blockIdx.x;
    int t = threadIdx.x;
    if (t < 120) h1[t] = g_buf6[b * 120 + t];
    __syncthreads();
    if (t < 84) {
        float acc = __ldg(b2 + t);
        const float* wr = w2 + t * 120;
#pragma unroll 4
        for (int c = 0; c < 120; c++) acc = fmaf(__ldg(wr + c), h1[c], acc);
        h2[t] = fmaxf(acc, 0.0f);
    }
    __syncthreads();
    if (t < 10) {
        float acc = __ldg(b3 + t);
        const float* wr = w3 + t * 84;
#pragma unroll 4
        for (int c = 0; c < 84; c++) acc = fmaf(__ldg(wr + c), h2[c], acc);
        out[b * 10 + t] = acc;
    }
}

// ---------------------------------------------------------------------------
extern "C" void kernel_launch(void* const* d_in, const int* in_sizes, int n_in,
                              void* d_out, int out_size) {
    const float* x     = (const float*)d_in[0];
    const float* dw1_w = (const float*)d_in[1];
    const float* dw1_b = (const float*)d_in[2];
    const float* pc1_w = (const float*)d_in[3];
    const float* pc1_b = (const float*)d_in[4];
    const float* dw2_w = (const float*)d_in[5];
    const float* dw2_b = (const float*)d_in[6];
    const float* pc2_w = (const float*)d_in[7];
    const float* pc2_b = (const float*)d_in[8];
    const float* oo_w  = (const float*)d_in[9];
    const float* oo_b  = (const float*)d_in[10];
    const float* fc1_w = (const float*)d_in[11];
    const float* fc1_b = (const float*)d_in[12];
    const float* fc2_w = (const float*)d_in[13];
    const float* fc2_b = (const float*)d_in[14];
    const float* fc3_w = (const float*)d_in[15];
    const float* fc3_b = (const float*)d_in[16];
    float* out = (float*)d_out;

    front_kernel<<<512, 256>>>(x, dw1_w, dw1_b, pc1_w, pc1_b, pc2_w, oo_w);

    dw2_kernel<<<BATCH * 13, 256>>>(dw2_w, dw2_b);

    pc2pool_kernel<<<BATCH * 15, 256>>>(pc2_b);

    oo_kernel<<<BATCH * 10, 256>>>(oo_b);

    fc1_kernel<<<120, 128>>>(fc1_w, fc1_b);

    fc_tail_kernel<<<BATCH, 128>>>(fc2_w, fc2_b, fc3_w, fc3_b, out);
}

// round 15
// speedup vs baseline: 1.0771x; 1.0771x over previous
#include <cuda_runtime.h>
#include <cuda_bf16.h>

// ---------------------------------------------------------------------------
// Net_80796924772492: small permuted-group CNN, B=64.
// front(dw1+pc1+relu+pool + init tail) -> dw2 -> pc2(+relu+pool, ldg weights)
//  -> oo 1x1 515->100 split-K RED into bias-seeded buffer
//  -> fc1(relu on load) -> fc2+fc3
// ---------------------------------------------------------------------------

#define BATCH 64

__device__ float g_buf2[BATCH * 51 * 14 * 14];   // front out
__device__ float g_buf3p[BATCH * 26000];         // dw2 out, [b][py5][260ch][20]
__device__ float g_buf4t[BATCH * 13100];         // pc2 out, [b][25 px][524 c]
__device__ float g_buf5[BATCH * 2500];           // oo out (bias-seeded, RED)
__device__ float g_buf6[BATCH * 120];            // fc1 out

// pc1 per-group info: (j, rep = i*ncpf+j, base = k*ncpf, 0)
__device__ int4 g_g1info[51];
// pc2 groups sorted by k, quads of 4 share k: slot -> (g, j, rep, base=k*51)
__device__ int4 g_g2sorted[524];
// pre-padded pc2 weights: [slot 524][52] (zero pad c=51, dup pad slots)
__device__ float g_w2pad[524 * 52];
// TRANSPOSED padded oo weights: [520 c][104 oc] (zero pads)
__device__ float g_oowT[520 * 104];

// ---------------------------------------------------------------------------
__device__ __forceinline__ int4 group_info1(int g) {   // F=6, ncpf=3
    int rem = g, i = 0;
    for (;;) {
        int cnt = (6 - i) + 2 * (5 - i);
        if (rem < cnt) break;
        rem -= cnt; i++;
    }
    int j, k;
    if (rem < 6 - i) { j = 0; k = i + rem; }
    else { rem -= (6 - i); j = 1 + rem / (5 - i); k = i + 1 + rem % (5 - i); }
    int4 r; r.x = j; r.y = i * 3 + j; r.z = k * 3; r.w = 0;
    return r;
}

__device__ __forceinline__ int4 slot_info2(int s) {
    const int qs[6] = {0, 1, 14, 40, 79, 131};
    const int Gk[5] = {1, 52, 103, 154, 205};
    int q = s >> 2;
    int k = 0;
    while (k < 4 && q >= qs[k + 1]) k++;
    int r = s - qs[k] * 4;
    if (r > Gk[k] - 1) r = Gk[k] - 1;       // pad: replicate last group
    int i, j;
    if (r <= k) { i = r; j = 0; }
    else { int r2 = r - (k + 1); i = r2 / 50; j = 1 + r2 % 50; }
    int base_i = 205 * i - 51 * (i * (i - 1) / 2);
    int off = (j == 0) ? (k - i) : (5 - i) + (j - 1) * (4 - i) + (k - i - 1);
    int4 v; v.x = base_i + off; v.y = j; v.z = i * 51 + j; v.w = k * 51;
    return v;
}

// init work: tables + padded weights + pad zeroing + bias-seed g_buf5.
__device__ void init_work(int ib, int tid,
                          const float* __restrict__ pc2_w,
                          const float* __restrict__ oo_w,
                          const float* __restrict__ oo_b) {
    const int CA = 51, CB = 524, CC = 524 * 52, CD = 520 * 104;
    const int CE = 64 * 225;    // g_buf4t pads: 25 px * 9 c
    const int CF = 64 * 500;    // g_buf3p pads: 5 py * 100
    const int CG = 64 * 2500;   // g_buf5 bias seed
    int total = CA + CB + CC + CD + CE + CF + CG;
    for (int t = ib * 256 + tid; t < total; t += 64 * 256) {
        int i = t;
        if (i < CA) { g_g1info[i] = group_info1(i); continue; }
        i -= CA;
        if (i < CB) { g_g2sorted[i] = slot_info2(i); continue; }
        i -= CB;
        if (i < CC) {
            int s = i / 52, c = i % 52;
            int g = slot_info2(s).x;
            g_w2pad[i] = (c < 51) ? __ldg(pc2_w + g * 51 + c) : 0.f;
            continue;
        }
        i -= CC;
        if (i < CD) {
            int c = i / 104, r = i % 104;   // transposed: [c][oc]
            g_oowT[i] = (r < 100 && c < 515) ? __ldg(oo_w + r * 515 + c) : 0.f;
            continue;
        }
        i -= CD;
        if (i < CE) {
            int b = i / 225, r = i % 225;
            int px = r / 9, c = 515 + r % 9;
            g_buf4t[b * 13100 + px * 524 + c] = 0.f;
            continue;
        }
        i -= CE;
        if (i < CF) {
            int b = i / 500, r = i % 500;
            int py = r / 100, q = r % 100;
            g_buf3p[b * 26000 + py * 5200 + 5100 + q] = 0.f;
            continue;
        }
        i -= CF;
        {
            int b = i / 2500, r = i % 2500;
            g_buf5[b * 2500 + r] = __ldg(oo_b + r / 25);
        }
    }
}

// ---------------------------------------------------------------------------
// front: dw1 + pc1 + relu + pool. Blocks 0..447 = (b, row-slice h of 7).
// Blocks 448..511 run init_work.
// ---------------------------------------------------------------------------
__global__ void front_kernel(const float* __restrict__ x,
                             const float* __restrict__ dw1_w,
                             const float* __restrict__ dw1_b,
                             const float* __restrict__ pc1_w,
                             const float* __restrict__ pc1_b,
                             const float* __restrict__ pc2_w,
                             const float* __restrict__ oo_w,
                             const float* __restrict__ oo_b) {
    __shared__ float sx[3 * 264];    // [ch][8 rows][pitch 33]
    __shared__ float sd[18 * 113];   // [oc][4 rows][28], pitch 113
    __shared__ float sw1[153];
    __shared__ float sb1[51];
    int tid = threadIdx.x;
    if (blockIdx.x >= 448) {
        init_work(blockIdx.x - 448, tid, pc2_w, oo_w, oo_b);
        return;
    }
    int b = blockIdx.x / 7, h = blockIdx.x % 7;
    int r0 = 4 * h;

    for (int i = tid; i < 768; i += 256) {
        int ch = i >> 8, t = i & 255;
        int rr = t >> 5, c = t & 31;
        sx[ch * 264 + rr * 33 + c] = x[(b * 3 + ch) * 1024 + (r0 + rr) * 32 + c];
    }
    if (tid < 153) sw1[tid] = __ldg(pc1_w + tid);
    if (tid >= 160 && tid < 211) sb1[tid - 160] = __ldg(pc1_b + tid - 160);
    __syncthreads();

    // dw1: 18 oc x 4 rows x 2 halves = 144 units (14-wide strips)
    if (tid < 144) {
        int xh = tid & 1;
        int t = tid >> 1;
        int row = t & 3, oc = t >> 2;
        int ci = oc / 6;
        const float* wp = dw1_w + oc * 25;
        float bb = __ldg(dw1_b + oc);
        float acc[14];
#pragma unroll
        for (int q = 0; q < 14; q++) acc[q] = bb;
        for (int ky = 0; ky < 5; ky++) {
            int rb = ci * 264 + (row + ky) * 33 + xh * 14;
            float r[18];
#pragma unroll
            for (int q = 0; q < 18; q++) r[q] = sx[rb + q];
#pragma unroll
            for (int kx = 0; kx < 5; kx++) {
                float ww = __ldg(wp + ky * 5 + kx);
#pragma unroll
                for (int xo = 0; xo < 14; xo++)
                    acc[xo] = fmaf(r[xo + kx], ww, acc[xo]);
            }
        }
        float* dst = sd + oc * 113 + row * 28 + xh * 14;
#pragma unroll
        for (int q = 0; q < 14; q++) dst[q] = acc[q];
    }
    __syncthreads();

    // pc1 + relu + pool: 51 g x 2 pooled rows x 14 px = 1428 units
    for (int u = tid; u < 1428; u += 256) {
        int px = u % 14;
        int t = u / 14;
        int pyl = t & 1, g = t >> 1;
        int4 gi = g_g1info[g];
        int ch0 = (gi.x == 0) ? gi.y : gi.z + 0;
        int ch1 = (gi.x == 1) ? gi.y : gi.z + 1;
        int ch2 = (gi.x == 2) ? gi.y : gi.z + 2;
        const float* p0 = sd + ch0 * 113;
        const float* p1 = sd + ch1 * 113;
        const float* p2 = sd + ch2 * 113;
        float w0 = sw1[g * 3 + 0], w1 = sw1[g * 3 + 1], w2 = sw1[g * 3 + 2];
        float bb = sb1[g];
        float m = 0.0f;
#pragma unroll
        for (int dy = 0; dy < 2; dy++) {
#pragma unroll
            for (int dx = 0; dx < 2; dx++) {
                int off = (2 * pyl + dy) * 28 + 2 * px + dx;
                float v = bb;
                v = fmaf(w0, p0[off], v);
                v = fmaf(w1, p1[off], v);
                v = fmaf(w2, p2[off], v);
                m = fmaxf(m, v);
            }
        }
        g_buf2[((b * 51 + g) * 14 + 2 * h + pyl) * 14 + px] = m;
    }
}

// ---------------------------------------------------------------------------
// dw2: [64,51,14,14] -> [b][py][260ch][20]. Block=(b, 4-ch chunk)x13.
// ---------------------------------------------------------------------------
__global__ void dw2_kernel(const float* __restrict__ w,
                           const float* __restrict__ bias) {
    __shared__ float s[4 * 200];
    int b = blockIdx.x / 13, chunk = blockIdx.x % 13;
    int c0 = chunk * 4;
    int nch = (chunk == 12) ? 3 : 4;
    int tid = threadIdx.x;
    const float* src = g_buf2 + (b * 51 + c0) * 196;
    int n = nch * 196;
    for (int i = tid; i < n; i += 256)
        s[(i / 196) * 200 + i % 196] = src[i];
    __syncthreads();

    int nu = nch * 50;
    if (tid < nu) {
        int ol = tid / 10, yo = tid % 10;
        int o = c0 * 5 + ol;
        int cil = ol / 5;
        const float* wp = w + o * 25;
        float bb = __ldg(bias + o);
        float acc[10];
#pragma unroll
        for (int t = 0; t < 10; t++) acc[t] = bb;
        for (int ky = 0; ky < 5; ky++) {
            int rb = cil * 200 + (yo + ky) * 14;
            float r[14];
#pragma unroll
            for (int t = 0; t < 14; t++) r[t] = s[rb + t];
#pragma unroll
            for (int kx = 0; kx < 5; kx++) {
                float ww = __ldg(wp + ky * 5 + kx);
#pragma unroll
                for (int xo = 0; xo < 10; xo++)
                    acc[xo] = fmaf(r[xo + kx], ww, acc[xo]);
            }
        }
        float* dst = g_buf3p + b * 26000 + (yo >> 1) * 5200 + o * 20 +
                     (yo & 1) * 10;
#pragma unroll
        for (int t = 0; t < 10; t++) dst[t] = acc[t];
    }
}

// ---------------------------------------------------------------------------
// pc2 + relu + pool:
//   out[g] = dot51(w[g], x[k-block]) + w[g,j]*(x[rep] - x[base+j])
// Thread = (quad, pooled px). Block = (b, py, third). Inputs in 20KB smem;
// weights read directly from L1-resident g_w2pad via __ldg.
// ---------------------------------------------------------------------------
__global__ __launch_bounds__(256, 4)
void pc2pool_kernel(const float* __restrict__ bias) {
    __shared__ float s_in[5120];     // 256 ch x 20
    int bid = blockIdx.x;
    int b = bid / 15;
    int t = bid % 15;
    int py = t / 3, part = t % 3;
    int q0 = part * 44;
    int nq = (part == 2) ? 43 : 44;
    int tid = threadIdx.x;

    {
        float4* si4 = (float4*)s_in;
        const float4* g4 = (const float4*)(g_buf3p + b * 26000 + py * 5200);
        for (int i = tid; i < 1280; i += 256) si4[i] = g4[i];
    }
    __syncthreads();

    int u = tid;
    if (u < nq * 5) {
        int ql = u / 5, px = u % 5;
        int slot0 = (q0 + ql) * 4;
        int base = g_g2sorted[slot0].w;
        const float4* wg = (const float4*)g_w2pad + slot0 * 13;
        float a[4][4];
#pragma unroll
        for (int s2 = 0; s2 < 4; s2++)
#pragma unroll
            for (int p = 0; p < 4; p++) a[s2][p] = 0.f;
        int xb = base * 20 + 2 * px;
#pragma unroll 2
        for (int cc4 = 0; cc4 < 13; cc4++) {
            float4 w0 = __ldg(wg + cc4);
            float4 w1 = __ldg(wg + 13 + cc4);
            float4 w2 = __ldg(wg + 26 + cc4);
            float4 w3 = __ldg(wg + 39 + cc4);
            float w0a[4] = {w0.x, w0.y, w0.z, w0.w};
            float w1a[4] = {w1.x, w1.y, w1.z, w1.w};
            float w2a[4] = {w2.x, w2.y, w2.z, w2.w};
            float w3a[4] = {w3.x, w3.y, w3.z, w3.w};
#pragma unroll
            for (int t2 = 0; t2 < 4; t2++) {
                int c = cc4 * 4 + t2;
                float2 top = *(const float2*)&s_in[xb + c * 20];
                float2 bot = *(const float2*)&s_in[xb + c * 20 + 10];
                a[0][0] = fmaf(w0a[t2], top.x, a[0][0]);
                a[0][1] = fmaf(w0a[t2], top.y, a[0][1]);
                a[0][2] = fmaf(w0a[t2], bot.x, a[0][2]);
                a[0][3] = fmaf(w0a[t2], bot.y, a[0][3]);
                a[1][0] = fmaf(w1a[t2], top.x, a[1][0]);
                a[1][1] = fmaf(w1a[t2], top.y, a[1][1]);
                a[1][2] = fmaf(w1a[t2], bot.x, a[1][2]);
                a[1][3] = fmaf(w1a[t2], bot.y, a[1][3]);
                a[2][0] = fmaf(w2a[t2], top.x, a[2][0]);
                a[2][1] = fmaf(w2a[t2], top.y, a[2][1]);
                a[2][2] = fmaf(w2a[t2], bot.x, a[2][2]);
                a[2][3] = fmaf(w2a[t2], bot.y, a[2][3]);
                a[3][0] = fmaf(w3a[t2], top.x, a[3][0]);
                a[3][1] = fmaf(w3a[t2], top.y, a[3][1]);
                a[3][2] = fmaf(w3a[t2], bot.x, a[3][2]);
                a[3][3] = fmaf(w3a[t2], bot.y, a[3][3]);
            }
        }
#pragma unroll
        for (int s2 = 0; s2 < 4; s2++) {
            int4 gi = g_g2sorted[slot0 + s2];
            float wj = __ldg(&g_w2pad[(slot0 + s2) * 52 + gi.y]);
            int rb2 = gi.z * 20 + 2 * px;
            int bb2 = (base + gi.y) * 20 + 2 * px;
            float2 rt = *(const float2*)&s_in[rb2];
            float2 rb_ = *(const float2*)&s_in[rb2 + 10];
            float2 bt = *(const float2*)&s_in[bb2];
            float2 bb_ = *(const float2*)&s_in[bb2 + 10];
            float v0 = fmaf(wj, rt.x - bt.x, a[s2][0]);
            float v1 = fmaf(wj, rt.y - bt.y, a[s2][1]);
            float v2 = fmaf(wj, rb_.x - bb_.x, a[s2][2]);
            float v3 = fmaf(wj, rb_.y - bb_.y, a[s2][3]);
            float m = fmaxf(fmaxf(v0, v1), fmaxf(v2, v3)) + __ldg(bias + gi.x);
            g_buf4t[b * 13100 + (py * 5 + px) * 524 + gi.x] = fmaxf(m, 0.f);
        }
    }
}

// ---------------------------------------------------------------------------
// oo split-K: 1x1 conv 515->100, partial sums over 260-channel halves,
// RED.ADD into bias-seeded g_buf5. Block = (b, px-group of 5, K-half),
// grid 640. x half-tile [5][260] in 5.2KB smem; weights coalesced float2
// __ldg from g_oowT. Relu happens in fc1 after combine.
// ---------------------------------------------------------------------------
__global__ __launch_bounds__(256, 6)
void oo_kernel() {
    __shared__ float xs[5 * 260];    // 5200 B
    int u = blockIdx.x;
    int b = u / 10;
    int r = u % 10;
    int pg = r >> 1, kh = r & 1;
    int c0 = kh * 260;
    int tid = threadIdx.x;

    {   // stage 5 rows x 65 float4 from g_buf4t[b][pg*5+pxl][c0..c0+260)
        float4* xs4 = (float4*)xs;
        const float* src = g_buf4t + b * 13100 + pg * 5 * 524 + c0;
        for (int i = tid; i < 325; i += 256) {
            int row = i / 65, col = i % 65;
            xs4[row * 65 + col] = *(const float4*)(src + row * 524 + col * 4);
        }
    }
    __syncthreads();

    if (tid < 250) {
        int ocp = tid % 50, pxl = tid / 50;   // warp: consecutive ocp
        int oc = ocp * 2;
        const float2* wT2 = (const float2*)g_oowT + c0 * 52;
        const float* xrow = xs + pxl * 260;
        float a0 = 0.f, a1 = 0.f;
#pragma unroll 4
        for (int cc = 0; cc < 260; cc += 4) {
            float4 xv = *(const float4*)&xrow[cc];
            float2 w0 = __ldg(wT2 + (cc + 0) * 52 + ocp);
            float2 w1 = __ldg(wT2 + (cc + 1) * 52 + ocp);
            float2 w2 = __ldg(wT2 + (cc + 2) * 52 + ocp);
            float2 w3 = __ldg(wT2 + (cc + 3) * 52 + ocp);
            a0 = fmaf(w0.x, xv.x, a0);
            a1 = fmaf(w0.y, xv.x, a1);
            a0 = fmaf(w1.x, xv.y, a0);
            a1 = fmaf(w1.y, xv.y, a1);
            a0 = fmaf(w2.x, xv.z, a0);
            a1 = fmaf(w2.y, xv.z, a1);
            a0 = fmaf(w3.x, xv.w, a0);
            a1 = fmaf(w3.y, xv.w, a1);
        }
        int pix = pg * 5 + pxl;
        float* dst = g_buf5 + b * 2500;
        atomicAdd(&dst[oc * 25 + pix], a0);
        atomicAdd(&dst[(oc + 1) * 25 + pix], a1);
    }
}

// ---------------------------------------------------------------------------
// fc1: x = relu(p) on load; [64,2500] x [120,2500]^T + bias, relu.
// Warp tile = 4 outputs x 4 batch (single buffer, R13 register shape).
// ---------------------------------------------------------------------------
__global__ void fc1_kernel(const float* __restrict__ w,
                           const float* __restrict__ bias) {
    int wid = (blockIdx.x * blockDim.x + threadIdx.x) >> 5;
    int lane = threadIdx.x & 31;
    if (wid >= 480) return;
    int o0 = (wid / 16) * 4;
    int b0 = (wid % 16) * 4;
    const float4* w4 = (const float4*)w;
    const float4* x4 = (const float4*)g_buf5;
    float a[16];
#pragma unroll
    for (int t = 0; t < 16; t++) a[t] = 0.f;
    for (int i = lane; i < 625; i += 32) {
        float4 wv[4], xv[4];
#pragma unroll
        for (int t = 0; t < 4; t++) wv[t] = __ldg(w4 + (o0 + t) * 625 + i);
#pragma unroll
        for (int t = 0; t < 4; t++) {
            float4 p = x4[(b0 + t) * 625 + i];
            xv[t].x = fmaxf(p.x, 0.f);
            xv[t].y = fmaxf(p.y, 0.f);
            xv[t].z = fmaxf(p.z, 0.f);
            xv[t].w = fmaxf(p.w, 0.f);
        }
#pragma unroll
        for (int oi = 0; oi < 4; oi++)
#pragma unroll
            for (int bi = 0; bi < 4; bi++) {
                a[oi * 4 + bi] = fmaf(wv[oi].x, xv[bi].x, a[oi * 4 + bi]);
                a[oi * 4 + bi] = fmaf(wv[oi].y, xv[bi].y, a[oi * 4 + bi]);
                a[oi * 4 + bi] = fmaf(wv[oi].z, xv[bi].z, a[oi * 4 + bi]);
                a[oi * 4 + bi] = fmaf(wv[oi].w, xv[bi].w, a[oi * 4 + bi]);
            }
    }
#pragma unroll
    for (int off = 16; off; off >>= 1)
#pragma unroll
        for (int t = 0; t < 16; t++)
            a[t] += __shfl_xor_sync(0xffffffffu, a[t], off);
    if (lane < 16) {
        int oi = lane >> 2, bi = lane & 3;
        g_buf6[(b0 + bi) * 120 + o0 + oi] =
            fmaxf(a[lane] + __ldg(bias + o0 + oi), 0.f);
    }
}

// ---------------------------------------------------------------------------
// fc2 (relu) + fc3 fused. block per batch element.
// ---------------------------------------------------------------------------
__global__ void fc_tail_kernel(const float* __restrict__ w2,
                               const float* __restrict__ b2,
                               const float* __restrict__ w3,
                               const float* __restrict__ b3,
                               float* __restrict__ out) {
    __shared__ float h1[120];
    __shared__ float h2[84];
    int b = blockIdx.x;
    int t = threadIdx.x;
    if (t < 120) h1[t] = g_buf6[b * 120 + t];
    __syncthreads();
    if (t < 84) {
        float acc = __ldg(b2 + t);
        const float* wr = w2 + t * 120;
#pragma unroll 4
        for (int c = 0; c < 120; c++) acc = fmaf(__ldg(wr + c), h1[c], acc);
        h2[t] = fmaxf(acc, 0.0f);
    }
    __syncthreads();
    if (t < 10) {
        float acc = __ldg(b3 + t);
        const float* wr = w3 + t * 84;
#pragma unroll 4
        for (int c = 0; c < 84; c++) acc = fmaf(__ldg(wr + c), h2[c], acc);
        out[b * 10 + t] = acc;
    }
}

// ---------------------------------------------------------------------------
extern "C" void kernel_launch(void* const* d_in, const int* in_sizes, int n_in,
                              void* d_out, int out_size) {
    const float* x     = (const float*)d_in[0];
    const float* dw1_w = (const float*)d_in[1];
    const float* dw1_b = (const float*)d_in[2];
    const float* pc1_w = (const float*)d_in[3];
    const float* pc1_b = (const float*)d_in[4];
    const float* dw2_w = (const float*)d_in[5];
    const float* dw2_b = (const float*)d_in[6];
    const float* pc2_w = (const float*)d_in[7];
    const float* pc2_b = (const float*)d_in[8];
    const float* oo_w  = (const float*)d_in[9];
    const float* oo_b  = (const float*)d_in[10];
    const float* fc1_w = (const float*)d_in[11];
    const float* fc1_b = (const float*)d_in[12];
    const float* fc2_w = (const float*)d_in[13];
    const float* fc2_b = (const float*)d_in[14];
    const float* fc3_w = (const float*)d_in[15];
    const float* fc3_b = (const float*)d_in[16];
    float* out = (float*)d_out;

    front_kernel<<<512, 256>>>(x, dw1_w, dw1_b, pc1_w, pc1_b,
                               pc2_w, oo_w, oo_b);

    dw2_kernel<<<BATCH * 13, 256>>>(dw2_w, dw2_b);

    pc2pool_kernel<<<BATCH * 15, 256>>>(pc2_b);

    oo_kernel<<<BATCH * 10, 256>>>();

    fc1_kernel<<<120, 128>>>(fc1_w, fc1_b);

    fc_tail_kernel<<<BATCH, 128>>>(fc2_w, fc2_b, fc3_w, fc3_b, out);
}

// round 16
// speedup vs baseline: 1.1394x; 1.0579x over previous
#include <cuda_runtime.h>
#include <cuda_bf16.h>

// ---------------------------------------------------------------------------
// Net_80796924772492: small permuted-group CNN, B=64.
// front(dw1+pc1+relu+pool + init tail) -> dw2 -> pc2(+relu+pool, ldg weights)
//  -> oo 1x1 515->100 quarter-K RED, thread tile 2oc x 5px
//  -> fc1(relu on load) -> fc2+fc3
// ---------------------------------------------------------------------------

#define BATCH 64

__device__ float g_buf2[BATCH * 51 * 14 * 14];   // front out
__device__ float g_buf3p[BATCH * 26000];         // dw2 out, [b][py5][260ch][20]
__device__ float g_buf4t[BATCH * 13100];         // pc2 out, [b][25 px][524 c]
__device__ float g_buf5[BATCH * 2500];           // oo out (bias-seeded, RED)
__device__ float g_buf6[BATCH * 120];            // fc1 out

// pc1 per-group info: (j, rep = i*ncpf+j, base = k*ncpf, 0)
__device__ int4 g_g1info[51];
// pc2 groups sorted by k, quads of 4 share k: slot -> (g, j, rep, base=k*51)
__device__ int4 g_g2sorted[524];
// pre-padded pc2 weights: [slot 524][52] (zero pad c=51, dup pad slots)
__device__ float g_w2pad[524 * 52];
// TRANSPOSED padded oo weights: [520 c][104 oc] (zero pads)
__device__ float g_oowT[520 * 104];

// ---------------------------------------------------------------------------
__device__ __forceinline__ int4 group_info1(int g) {   // F=6, ncpf=3
    int rem = g, i = 0;
    for (;;) {
        int cnt = (6 - i) + 2 * (5 - i);
        if (rem < cnt) break;
        rem -= cnt; i++;
    }
    int j, k;
    if (rem < 6 - i) { j = 0; k = i + rem; }
    else { rem -= (6 - i); j = 1 + rem / (5 - i); k = i + 1 + rem % (5 - i); }
    int4 r; r.x = j; r.y = i * 3 + j; r.z = k * 3; r.w = 0;
    return r;
}

__device__ __forceinline__ int4 slot_info2(int s) {
    const int qs[6] = {0, 1, 14, 40, 79, 131};
    const int Gk[5] = {1, 52, 103, 154, 205};
    int q = s >> 2;
    int k = 0;
    while (k < 4 && q >= qs[k + 1]) k++;
    int r = s - qs[k] * 4;
    if (r > Gk[k] - 1) r = Gk[k] - 1;       // pad: replicate last group
    int i, j;
    if (r <= k) { i = r; j = 0; }
    else { int r2 = r - (k + 1); i = r2 / 50; j = 1 + r2 % 50; }
    int base_i = 205 * i - 51 * (i * (i - 1) / 2);
    int off = (j == 0) ? (k - i) : (5 - i) + (j - 1) * (4 - i) + (k - i - 1);
    int4 v; v.x = base_i + off; v.y = j; v.z = i * 51 + j; v.w = k * 51;
    return v;
}

// init work: tables + padded weights + pad zeroing + bias-seed g_buf5.
__device__ void init_work(int ib, int tid,
                          const float* __restrict__ pc2_w,
                          const float* __restrict__ oo_w,
                          const float* __restrict__ oo_b) {
    const int CA = 51, CB = 524, CC = 524 * 52, CD = 520 * 104;
    const int CE = 64 * 225;    // g_buf4t pads: 25 px * 9 c
    const int CF = 64 * 500;    // g_buf3p pads: 5 py * 100
    const int CG = 64 * 2500;   // g_buf5 bias seed
    int total = CA + CB + CC + CD + CE + CF + CG;
    for (int t = ib * 256 + tid; t < total; t += 64 * 256) {
        int i = t;
        if (i < CA) { g_g1info[i] = group_info1(i); continue; }
        i -= CA;
        if (i < CB) { g_g2sorted[i] = slot_info2(i); continue; }
        i -= CB;
        if (i < CC) {
            int s = i / 52, c = i % 52;
            int g = slot_info2(s).x;
            g_w2pad[i] = (c < 51) ? __ldg(pc2_w + g * 51 + c) : 0.f;
            continue;
        }
        i -= CC;
        if (i < CD) {
            int c = i / 104, r = i % 104;   // transposed: [c][oc]
            g_oowT[i] = (r < 100 && c < 515) ? __ldg(oo_w + r * 515 + c) : 0.f;
            continue;
        }
        i -= CD;
        if (i < CE) {
            int b = i / 225, r = i % 225;
            int px = r / 9, c = 515 + r % 9;
            g_buf4t[b * 13100 + px * 524 + c] = 0.f;
            continue;
        }
        i -= CE;
        if (i < CF) {
            int b = i / 500, r = i % 500;
            int py = r / 100, q = r % 100;
            g_buf3p[b * 26000 + py * 5200 + 5100 + q] = 0.f;
            continue;
        }
        i -= CF;
        {
            int b = i / 2500, r = i % 2500;
            g_buf5[b * 2500 + r] = __ldg(oo_b + r / 25);
        }
    }
}

// ---------------------------------------------------------------------------
// front: dw1 + pc1 + relu + pool. Blocks 0..447 = (b, row-slice h of 7).
// Blocks 448..511 run init_work.
// ---------------------------------------------------------------------------
__global__ void front_kernel(const float* __restrict__ x,
                             const float* __restrict__ dw1_w,
                             const float* __restrict__ dw1_b,
                             const float* __restrict__ pc1_w,
                             const float* __restrict__ pc1_b,
                             const float* __restrict__ pc2_w,
                             const float* __restrict__ oo_w,
                             const float* __restrict__ oo_b) {
    __shared__ float sx[3 * 264];    // [ch][8 rows][pitch 33]
    __shared__ float sd[18 * 113];   // [oc][4 rows][28], pitch 113
    __shared__ float sw1[153];
    __shared__ float sb1[51];
    int tid = threadIdx.x;
    if (blockIdx.x >= 448) {
        init_work(blockIdx.x - 448, tid, pc2_w, oo_w, oo_b);
        return;
    }
    int b = blockIdx.x / 7, h = blockIdx.x % 7;
    int r0 = 4 * h;

    for (int i = tid; i < 768; i += 256) {
        int ch = i >> 8, t = i & 255;
        int rr = t >> 5, c = t & 31;
        sx[ch * 264 + rr * 33 + c] = x[(b * 3 + ch) * 1024 + (r0 + rr) * 32 + c];
    }
    if (tid < 153) sw1[tid] = __ldg(pc1_w + tid);
    if (tid >= 160 && tid < 211) sb1[tid - 160] = __ldg(pc1_b + tid - 160);
    __syncthreads();

    // dw1: 18 oc x 4 rows x 2 halves = 144 units (14-wide strips)
    if (tid < 144) {
        int xh = tid & 1;
        int t = tid >> 1;
        int row = t & 3, oc = t >> 2;
        int ci = oc / 6;
        const float* wp = dw1_w + oc * 25;
        float bb = __ldg(dw1_b + oc);
        float acc[14];
#pragma unroll
        for (int q = 0; q < 14; q++) acc[q] = bb;
        for (int ky = 0; ky < 5; ky++) {
            int rb = ci * 264 + (row + ky) * 33 + xh * 14;
            float r[18];
#pragma unroll
            for (int q = 0; q < 18; q++) r[q] = sx[rb + q];
#pragma unroll
            for (int kx = 0; kx < 5; kx++) {
                float ww = __ldg(wp + ky * 5 + kx);
#pragma unroll
                for (int xo = 0; xo < 14; xo++)
                    acc[xo] = fmaf(r[xo + kx], ww, acc[xo]);
            }
        }
        float* dst = sd + oc * 113 + row * 28 + xh * 14;
#pragma unroll
        for (int q = 0; q < 14; q++) dst[q] = acc[q];
    }
    __syncthreads();

    // pc1 + relu + pool: 51 g x 2 pooled rows x 14 px = 1428 units
    for (int u = tid; u < 1428; u += 256) {
        int px = u % 14;
        int t = u / 14;
        int pyl = t & 1, g = t >> 1;
        int4 gi = g_g1info[g];
        int ch0 = (gi.x == 0) ? gi.y : gi.z + 0;
        int ch1 = (gi.x == 1) ? gi.y : gi.z + 1;
        int ch2 = (gi.x == 2) ? gi.y : gi.z + 2;
        const float* p0 = sd + ch0 * 113;
        const float* p1 = sd + ch1 * 113;
        const float* p2 = sd + ch2 * 113;
        float w0 = sw1[g * 3 + 0], w1 = sw1[g * 3 + 1], w2 = sw1[g * 3 + 2];
        float bb = sb1[g];
        float m = 0.0f;
#pragma unroll
        for (int dy = 0; dy < 2; dy++) {
#pragma unroll
            for (int dx = 0; dx < 2; dx++) {
                int off = (2 * pyl + dy) * 28 + 2 * px + dx;
                float v = bb;
                v = fmaf(w0, p0[off], v);
                v = fmaf(w1, p1[off], v);
                v = fmaf(w2, p2[off], v);
                m = fmaxf(m, v);
            }
        }
        g_buf2[((b * 51 + g) * 14 + 2 * h + pyl) * 14 + px] = m;
    }
}

// ---------------------------------------------------------------------------
// dw2: [64,51,14,14] -> [b][py][260ch][20]. Block=(b, 4-ch chunk)x13.
// ---------------------------------------------------------------------------
__global__ void dw2_kernel(const float* __restrict__ w,
                           const float* __restrict__ bias) {
    __shared__ float s[4 * 200];
    int b = blockIdx.x / 13, chunk = blockIdx.x % 13;
    int c0 = chunk * 4;
    int nch = (chunk == 12) ? 3 : 4;
    int tid = threadIdx.x;
    const float* src = g_buf2 + (b * 51 + c0) * 196;
    int n = nch * 196;
    for (int i = tid; i < n; i += 256)
        s[(i / 196) * 200 + i % 196] = src[i];
    __syncthreads();

    int nu = nch * 50;
    if (tid < nu) {
        int ol = tid / 10, yo = tid % 10;
        int o = c0 * 5 + ol;
        int cil = ol / 5;
        const float* wp = w + o * 25;
        float bb = __ldg(bias + o);
        float acc[10];
#pragma unroll
        for (int t = 0; t < 10; t++) acc[t] = bb;
        for (int ky = 0; ky < 5; ky++) {
            int rb = cil * 200 + (yo + ky) * 14;
            float r[14];
#pragma unroll
            for (int t = 0; t < 14; t++) r[t] = s[rb + t];
#pragma unroll
            for (int kx = 0; kx < 5; kx++) {
                float ww = __ldg(wp + ky * 5 + kx);
#pragma unroll
                for (int xo = 0; xo < 10; xo++)
                    acc[xo] = fmaf(r[xo + kx], ww, acc[xo]);
            }
        }
        float* dst = g_buf3p + b * 26000 + (yo >> 1) * 5200 + o * 20 +
                     (yo & 1) * 10;
#pragma unroll
        for (int t = 0; t < 10; t++) dst[t] = acc[t];
    }
}

// ---------------------------------------------------------------------------
// pc2 + relu + pool:
//   out[g] = dot51(w[g], x[k-block]) + w[g,j]*(x[rep] - x[base+j])
// Thread = (quad, pooled px). Block = (b, py, third). Inputs in 20KB smem;
// weights read directly from L1-resident g_w2pad via __ldg.
// ---------------------------------------------------------------------------
__global__ __launch_bounds__(256, 4)
void pc2pool_kernel(const float* __restrict__ bias) {
    __shared__ float s_in[5120];     // 256 ch x 20
    int bid = blockIdx.x;
    int b = bid / 15;
    int t = bid % 15;
    int py = t / 3, part = t % 3;
    int q0 = part * 44;
    int nq = (part == 2) ? 43 : 44;
    int tid = threadIdx.x;

    {
        float4* si4 = (float4*)s_in;
        const float4* g4 = (const float4*)(g_buf3p + b * 26000 + py * 5200);
        for (int i = tid; i < 1280; i += 256) si4[i] = g4[i];
    }
    __syncthreads();

    int u = tid;
    if (u < nq * 5) {
        int ql = u / 5, px = u % 5;
        int slot0 = (q0 + ql) * 4;
        int base = g_g2sorted[slot0].w;
        const float4* wg = (const float4*)g_w2pad + slot0 * 13;
        float a[4][4];
#pragma unroll
        for (int s2 = 0; s2 < 4; s2++)
#pragma unroll
            for (int p = 0; p < 4; p++) a[s2][p] = 0.f;
        int xb = base * 20 + 2 * px;
#pragma unroll 2
        for (int cc4 = 0; cc4 < 13; cc4++) {
            float4 w0 = __ldg(wg + cc4);
            float4 w1 = __ldg(wg + 13 + cc4);
            float4 w2 = __ldg(wg + 26 + cc4);
            float4 w3 = __ldg(wg + 39 + cc4);
            float w0a[4] = {w0.x, w0.y, w0.z, w0.w};
            float w1a[4] = {w1.x, w1.y, w1.z, w1.w};
            float w2a[4] = {w2.x, w2.y, w2.z, w2.w};
            float w3a[4] = {w3.x, w3.y, w3.z, w3.w};
#pragma unroll
            for (int t2 = 0; t2 < 4; t2++) {
                int c = cc4 * 4 + t2;
                float2 top = *(const float2*)&s_in[xb + c * 20];
                float2 bot = *(const float2*)&s_in[xb + c * 20 + 10];
                a[0][0] = fmaf(w0a[t2], top.x, a[0][0]);
                a[0][1] = fmaf(w0a[t2], top.y, a[0][1]);
                a[0][2] = fmaf(w0a[t2], bot.x, a[0][2]);
                a[0][3] = fmaf(w0a[t2], bot.y, a[0][3]);
                a[1][0] = fmaf(w1a[t2], top.x, a[1][0]);
                a[1][1] = fmaf(w1a[t2], top.y, a[1][1]);
                a[1][2] = fmaf(w1a[t2], bot.x, a[1][2]);
                a[1][3] = fmaf(w1a[t2], bot.y, a[1][3]);
                a[2][0] = fmaf(w2a[t2], top.x, a[2][0]);
                a[2][1] = fmaf(w2a[t2], top.y, a[2][1]);
                a[2][2] = fmaf(w2a[t2], bot.x, a[2][2]);
                a[2][3] = fmaf(w2a[t2], bot.y, a[2][3]);
                a[3][0] = fmaf(w3a[t2], top.x, a[3][0]);
                a[3][1] = fmaf(w3a[t2], top.y, a[3][1]);
                a[3][2] = fmaf(w3a[t2], bot.x, a[3][2]);
                a[3][3] = fmaf(w3a[t2], bot.y, a[3][3]);
            }
        }
#pragma unroll
        for (int s2 = 0; s2 < 4; s2++) {
            int4 gi = g_g2sorted[slot0 + s2];
            float wj = __ldg(&g_w2pad[(slot0 + s2) * 52 + gi.y]);
            int rb2 = gi.z * 20 + 2 * px;
            int bb2 = (base + gi.y) * 20 + 2 * px;
            float2 rt = *(const float2*)&s_in[rb2];
            float2 rb_ = *(const float2*)&s_in[rb2 + 10];
            float2 bt = *(const float2*)&s_in[bb2];
            float2 bb_ = *(const float2*)&s_in[bb2 + 10];
            float v0 = fmaf(wj, rt.x - bt.x, a[s2][0]);
            float v1 = fmaf(wj, rt.y - bt.y, a[s2][1]);
            float v2 = fmaf(wj, rb_.x - bb_.x, a[s2][2]);
            float v3 = fmaf(wj, rb_.y - bb_.y, a[s2][3]);
            float m = fmaxf(fmaxf(v0, v1), fmaxf(v2, v3)) + __ldg(bias + gi.x);
            g_buf4t[b * 13100 + (py * 5 + px) * 524 + gi.x] = fmaxf(m, 0.f);
        }
    }
}

// ---------------------------------------------------------------------------
// oo quarter-K: 1x1 conv 515->100 partials, RED.ADD into bias-seeded g_buf5.
// Block = (b, K-quarter, oc-half) -> grid 512 x 128 threads.
// K slices: {132,132,132,128} channels (16B-aligned starts; pads zero).
// x slice [25 px][132 c] in 13.2KB smem. Thread = 2 oc x 5 px: weights
// amortized over 5 pixels (FMA:LDG = 10). Relu happens in fc1.
// ---------------------------------------------------------------------------
__global__ __launch_bounds__(128)
void oo_kernel() {
    __shared__ float xs[25 * 132];   // 13.2 KB
    int u = blockIdx.x;
    int b = u >> 3;
    int r = u & 7;
    int kq = r >> 1, oh = r & 1;
    int c0 = kq * 132;
    int nch = (kq == 3) ? 128 : 132;
    int nf4 = nch >> 2;              // 33 or 32
    int tid = threadIdx.x;

    {   // stage 25 rows x nf4 float4
        const float* src = g_buf4t + b * 13100 + c0;
        int n = 25 * nf4;
        for (int i = tid; i < n; i += 128) {
            int row = i / nf4, col = (i % nf4) * 4;
            *(float4*)&xs[row * 132 + col] =
                *(const float4*)(src + row * 524 + col);
        }
    }
    __syncthreads();

    if (tid < 125) {
        int pxg = tid / 25;              // 0..4
        int ocp = oh * 25 + (tid - pxg * 25);
        int oc = ocp * 2;
        const float2* wT2 = (const float2*)g_oowT + c0 * 52 + ocp;
        const float* x0 = xs + pxg * 5 * 132;
        float a0[5] = {0.f, 0.f, 0.f, 0.f, 0.f};
        float a1[5] = {0.f, 0.f, 0.f, 0.f, 0.f};
        for (int cc = 0; cc < nch; cc += 4) {
            float2 w0 = __ldg(wT2 + (cc + 0) * 52);
            float2 w1 = __ldg(wT2 + (cc + 1) * 52);
            float2 w2 = __ldg(wT2 + (cc + 2) * 52);
            float2 w3 = __ldg(wT2 + (cc + 3) * 52);
#pragma unroll
            for (int p = 0; p < 5; p++) {
                float4 xv = *(const float4*)&x0[p * 132 + cc];
                a0[p] = fmaf(w0.x, xv.x, a0[p]);
                a1[p] = fmaf(w0.y, xv.x, a1[p]);
                a0[p] = fmaf(w1.x, xv.y, a0[p]);
                a1[p] = fmaf(w1.y, xv.y, a1[p]);
                a0[p] = fmaf(w2.x, xv.z, a0[p]);
                a1[p] = fmaf(w2.y, xv.z, a1[p]);
                a0[p] = fmaf(w3.x, xv.w, a0[p]);
                a1[p] = fmaf(w3.y, xv.w, a1[p]);
            }
        }
        float* dst = g_buf5 + b * 2500;
#pragma unroll
        for (int p = 0; p < 5; p++) {
            int pix = pxg * 5 + p;
            atomicAdd(&dst[oc * 25 + pix], a0[p]);
            atomicAdd(&dst[(oc + 1) * 25 + pix], a1[p]);
        }
    }
}

// ---------------------------------------------------------------------------
// fc1: x = relu(p) on load; [64,2500] x [120,2500]^T + bias, relu.
// Warp tile = 4 outputs x 4 batch.
// ---------------------------------------------------------------------------
__global__ void fc1_kernel(const float* __restrict__ w,
                           const float* __restrict__ bias) {
    int wid = (blockIdx.x * blockDim.x + threadIdx.x) >> 5;
    int lane = threadIdx.x & 31;
    if (wid >= 480) return;
    int o0 = (wid / 16) * 4;
    int b0 = (wid % 16) * 4;
    const float4* w4 = (const float4*)w;
    const float4* x4 = (const float4*)g_buf5;
    float a[16];
#pragma unroll
    for (int t = 0; t < 16; t++) a[t] = 0.f;
    for (int i = lane; i < 625; i += 32) {
        float4 wv[4], xv[4];
#pragma unroll
        for (int t = 0; t < 4; t++) wv[t] = __ldg(w4 + (o0 + t) * 625 + i);
#pragma unroll
        for (int t = 0; t < 4; t++) {
            float4 p = x4[(b0 + t) * 625 + i];
            xv[t].x = fmaxf(p.x, 0.f);
            xv[t].y = fmaxf(p.y, 0.f);
            xv[t].z = fmaxf(p.z, 0.f);
            xv[t].w = fmaxf(p.w, 0.f);
        }
#pragma unroll
        for (int oi = 0; oi < 4; oi++)
#pragma unroll
            for (int bi = 0; bi < 4; bi++) {
                a[oi * 4 + bi] = fmaf(wv[oi].x, xv[bi].x, a[oi * 4 + bi]);
                a[oi * 4 + bi] = fmaf(wv[oi].y, xv[bi].y, a[oi * 4 + bi]);
                a[oi * 4 + bi] = fmaf(wv[oi].z, xv[bi].z, a[oi * 4 + bi]);
                a[oi * 4 + bi] = fmaf(wv[oi].w, xv[bi].w, a[oi * 4 + bi]);
            }
    }
#pragma unroll
    for (int off = 16; off; off >>= 1)
#pragma unroll
        for (int t = 0; t < 16; t++)
            a[t] += __shfl_xor_sync(0xffffffffu, a[t], off);
    if (lane < 16) {
        int oi = lane >> 2, bi = lane & 3;
        g_buf6[(b0 + bi) * 120 + o0 + oi] =
            fmaxf(a[lane] + __ldg(bias + o0 + oi), 0.f);
    }
}

// ---------------------------------------------------------------------------
// fc2 (relu) + fc3 fused. block per batch element.
// ---------------------------------------------------------------------------
__global__ void fc_tail_kernel(const float* __restrict__ w2,
                               const float* __restrict__ b2,
                               const float* __restrict__ w3,
                               const float* __restrict__ b3,
                               float* __restrict__ out) {
    __shared__ float h1[120];
    __shared__ float h2[84];
    int b = blockIdx.x;
    int t = threadIdx.x;
    if (t < 120) h1[t] = g_buf6[b * 120 + t];
    __syncthreads();
    if (t < 84) {
        float acc = __ldg(b2 + t);
        const float* wr = w2 + t * 120;
#pragma unroll 4
        for (int c = 0; c < 120; c++) acc = fmaf(__ldg(wr + c), h1[c], acc);
        h2[t] = fmaxf(acc, 0.0f);
    }
    __syncthreads();
    if (t < 10) {
        float acc = __ldg(b3 + t);
        const float* wr = w3 + t * 84;
#pragma unroll 4
        for (int c = 0; c < 84; c++) acc = fmaf(__ldg(wr + c), h2[c], acc);
        out[b * 10 + t] = acc;
    }
}

// ---------------------------------------------------------------------------
extern "C" void kernel_launch(void* const* d_in, const int* in_sizes, int n_in,
                              void* d_out, int out_size) {
    const float* x     = (const float*)d_in[0];
    const float* dw1_w = (const float*)d_in[1];
    const float* dw1_b = (const float*)d_in[2];
    const float* pc1_w = (const float*)d_in[3];
    const float* pc1_b = (const float*)d_in[4];
    const float* dw2_w = (const float*)d_in[5];
    const float* dw2_b = (const float*)d_in[6];
    const float* pc2_w = (const float*)d_in[7];
    const float* pc2_b = (const float*)d_in[8];
    const float* oo_w  = (const float*)d_in[9];
    const float* oo_b  = (const float*)d_in[10];
    const float* fc1_w = (const float*)d_in[11];
    const float* fc1_b = (const float*)d_in[12];
    const float* fc2_w = (const float*)d_in[13];
    const float* fc2_b = (const float*)d_in[14];
    const float* fc3_w = (const float*)d_in[15];
    const float* fc3_b = (const float*)d_in[16];
    float* out = (float*)d_out;

    front_kernel<<<512, 256>>>(x, dw1_w, dw1_b, pc1_w, pc1_b,
                               pc2_w, oo_w, oo_b);

    dw2_kernel<<<BATCH * 13, 256>>>(dw2_w, dw2_b);

    pc2pool_kernel<<<BATCH * 15, 256>>>(pc2_b);

    oo_kernel<<<512, 128>>>();

    fc1_kernel<<<120, 128>>>(fc1_w, fc1_b);

    fc_tail_kernel<<<BATCH, 128>>>(fc2_w, fc2_b, fc3_w, fc3_b, out);
}

// round 17
// speedup vs baseline: 1.1750x; 1.0312x over previous
#include <cuda_runtime.h>
#include <cuda_bf16.h>

// ---------------------------------------------------------------------------
// Net_80796924772492: small permuted-group CNN, B=64.
// front(dw1+pc1+relu+pool + init tail) -> dw2 -> pc2(+relu+pool, ldg weights)
//  -> oo 1x1 515->100 quarter-K RED, all-smem inner loop
//  -> fc1(relu on load) -> fc2+fc3
// ---------------------------------------------------------------------------

#define BATCH 64

__device__ float g_buf2[BATCH * 51 * 14 * 14];   // front out
__device__ float g_buf3p[BATCH * 26000];         // dw2 out, [b][py5][260ch][20]
__device__ float g_buf4t[BATCH * 13100];         // pc2 out, [b][25 px][524 c]
__device__ float g_buf5[BATCH * 2500];           // oo out (bias-seeded, RED)
__device__ float g_buf6[BATCH * 120];            // fc1 out

// pc1 per-group info: (j, rep = i*ncpf+j, base = k*ncpf, 0)
__device__ int4 g_g1info[51];
// pc2 groups sorted by k, quads of 4 share k: slot -> (g, j, rep, base=k*51)
__device__ int4 g_g2sorted[524];
// pre-padded pc2 weights: [slot 524][52] (zero pad c=51, dup pad slots)
__device__ float g_w2pad[524 * 52];
// TRANSPOSED padded oo weights: [520 c][104 oc] (zero pads)
__device__ float g_oowT[520 * 104];

// ---------------------------------------------------------------------------
__device__ __forceinline__ int4 group_info1(int g) {   // F=6, ncpf=3
    int rem = g, i = 0;
    for (;;) {
        int cnt = (6 - i) + 2 * (5 - i);
        if (rem < cnt) break;
        rem -= cnt; i++;
    }
    int j, k;
    if (rem < 6 - i) { j = 0; k = i + rem; }
    else { rem -= (6 - i); j = 1 + rem / (5 - i); k = i + 1 + rem % (5 - i); }
    int4 r; r.x = j; r.y = i * 3 + j; r.z = k * 3; r.w = 0;
    return r;
}

__device__ __forceinline__ int4 slot_info2(int s) {
    const int qs[6] = {0, 1, 14, 40, 79, 131};
    const int Gk[5] = {1, 52, 103, 154, 205};
    int q = s >> 2;
    int k = 0;
    while (k < 4 && q >= qs[k + 1]) k++;
    int r = s - qs[k] * 4;
    if (r > Gk[k] - 1) r = Gk[k] - 1;       // pad: replicate last group
    int i, j;
    if (r <= k) { i = r; j = 0; }
    else { int r2 = r - (k + 1); i = r2 / 50; j = 1 + r2 % 50; }
    int base_i = 205 * i - 51 * (i * (i - 1) / 2);
    int off = (j == 0) ? (k - i) : (5 - i) + (j - 1) * (4 - i) + (k - i - 1);
    int4 v; v.x = base_i + off; v.y = j; v.z = i * 51 + j; v.w = k * 51;
    return v;
}

// init work: tables + padded weights + pad zeroing + bias-seed g_buf5.
__device__ void init_work(int ib, int tid,
                          const float* __restrict__ pc2_w,
                          const float* __restrict__ oo_w,
                          const float* __restrict__ oo_b) {
    const int CA = 51, CB = 524, CC = 524 * 52, CD = 520 * 104;
    const int CE = 64 * 225;    // g_buf4t pads: 25 px * 9 c
    const int CF = 64 * 500;    // g_buf3p pads: 5 py * 100
    const int CG = 64 * 2500;   // g_buf5 bias seed
    int total = CA + CB + CC + CD + CE + CF + CG;
    for (int t = ib * 256 + tid; t < total; t += 64 * 256) {
        int i = t;
        if (i < CA) { g_g1info[i] = group_info1(i); continue; }
        i -= CA;
        if (i < CB) { g_g2sorted[i] = slot_info2(i); continue; }
        i -= CB;
        if (i < CC) {
            int s = i / 52, c = i % 52;
            int g = slot_info2(s).x;
            g_w2pad[i] = (c < 51) ? __ldg(pc2_w + g * 51 + c) : 0.f;
            continue;
        }
        i -= CC;
        if (i < CD) {
            int c = i / 104, r = i % 104;   // transposed: [c][oc]
            g_oowT[i] = (r < 100 && c < 515) ? __ldg(oo_w + r * 515 + c) : 0.f;
            continue;
        }
        i -= CD;
        if (i < CE) {
            int b = i / 225, r = i % 225;
            int px = r / 9, c = 515 + r % 9;
            g_buf4t[b * 13100 + px * 524 + c] = 0.f;
            continue;
        }
        i -= CE;
        if (i < CF) {
            int b = i / 500, r = i % 500;
            int py = r / 100, q = r % 100;
            g_buf3p[b * 26000 + py * 5200 + 5100 + q] = 0.f;
            continue;
        }
        i -= CF;
        {
            int b = i / 2500, r = i % 2500;
            g_buf5[b * 2500 + r] = __ldg(oo_b + r / 25);
        }
    }
}

// ---------------------------------------------------------------------------
// front: dw1 + pc1 + relu + pool. Blocks 0..447 = (b, row-slice h of 7).
// Blocks 448..511 run init_work.
// ---------------------------------------------------------------------------
__global__ void front_kernel(const float* __restrict__ x,
                             const float* __restrict__ dw1_w,
                             const float* __restrict__ dw1_b,
                             const float* __restrict__ pc1_w,
                             const float* __restrict__ pc1_b,
                             const float* __restrict__ pc2_w,
                             const float* __restrict__ oo_w,
                             const float* __restrict__ oo_b) {
    __shared__ float sx[3 * 264];    // [ch][8 rows][pitch 33]
    __shared__ float sd[18 * 113];   // [oc][4 rows][28], pitch 113
    __shared__ float sw1[153];
    __shared__ float sb1[51];
    int tid = threadIdx.x;
    if (blockIdx.x >= 448) {
        init_work(blockIdx.x - 448, tid, pc2_w, oo_w, oo_b);
        return;
    }
    int b = blockIdx.x / 7, h = blockIdx.x % 7;
    int r0 = 4 * h;

    for (int i = tid; i < 768; i += 256) {
        int ch = i >> 8, t = i & 255;
        int rr = t >> 5, c = t & 31;
        sx[ch * 264 + rr * 33 + c] = x[(b * 3 + ch) * 1024 + (r0 + rr) * 32 + c];
    }
    if (tid < 153) sw1[tid] = __ldg(pc1_w + tid);
    if (tid >= 160 && tid < 211) sb1[tid - 160] = __ldg(pc1_b + tid - 160);
    __syncthreads();

    // dw1: 18 oc x 4 rows x 2 halves = 144 units (14-wide strips)
    if (tid < 144) {
        int xh = tid & 1;
        int t = tid >> 1;
        int row = t & 3, oc = t >> 2;
        int ci = oc / 6;
        const float* wp = dw1_w + oc * 25;
        float bb = __ldg(dw1_b + oc);
        float acc[14];
#pragma unroll
        for (int q = 0; q < 14; q++) acc[q] = bb;
        for (int ky = 0; ky < 5; ky++) {
            int rb = ci * 264 + (row + ky) * 33 + xh * 14;
            float r[18];
#pragma unroll
            for (int q = 0; q < 18; q++) r[q] = sx[rb + q];
#pragma unroll
            for (int kx = 0; kx < 5; kx++) {
                float ww = __ldg(wp + ky * 5 + kx);
#pragma unroll
                for (int xo = 0; xo < 14; xo++)
                    acc[xo] = fmaf(r[xo + kx], ww, acc[xo]);
            }
        }
        float* dst = sd + oc * 113 + row * 28 + xh * 14;
#pragma unroll
        for (int q = 0; q < 14; q++) dst[q] = acc[q];
    }
    __syncthreads();

    // pc1 + relu + pool: 51 g x 2 pooled rows x 14 px = 1428 units
    for (int u = tid; u < 1428; u += 256) {
        int px = u % 14;
        int t = u / 14;
        int pyl = t & 1, g = t >> 1;
        int4 gi = g_g1info[g];
        int ch0 = (gi.x == 0) ? gi.y : gi.z + 0;
        int ch1 = (gi.x == 1) ? gi.y : gi.z + 1;
        int ch2 = (gi.x == 2) ? gi.y : gi.z + 2;
        const float* p0 = sd + ch0 * 113;
        const float* p1 = sd + ch1 * 113;
        const float* p2 = sd + ch2 * 113;
        float w0 = sw1[g * 3 + 0], w1 = sw1[g * 3 + 1], w2 = sw1[g * 3 + 2];
        float bb = sb1[g];
        float m = 0.0f;
#pragma unroll
        for (int dy = 0; dy < 2; dy++) {
#pragma unroll
            for (int dx = 0; dx < 2; dx++) {
                int off = (2 * pyl + dy) * 28 + 2 * px + dx;
                float v = bb;
                v = fmaf(w0, p0[off], v);
                v = fmaf(w1, p1[off], v);
                v = fmaf(w2, p2[off], v);
                m = fmaxf(m, v);
            }
        }
        g_buf2[((b * 51 + g) * 14 + 2 * h + pyl) * 14 + px] = m;
    }
}

// ---------------------------------------------------------------------------
// dw2: [64,51,14,14] -> [b][py][260ch][20]. Block=(b, 4-ch chunk)x13.
// ---------------------------------------------------------------------------
__global__ void dw2_kernel(const float* __restrict__ w,
                           const float* __restrict__ bias) {
    __shared__ float s[4 * 200];
    int b = blockIdx.x / 13, chunk = blockIdx.x % 13;
    int c0 = chunk * 4;
    int nch = (chunk == 12) ? 3 : 4;
    int tid = threadIdx.x;
    const float* src = g_buf2 + (b * 51 + c0) * 196;
    int n = nch * 196;
    for (int i = tid; i < n; i += 256)
        s[(i / 196) * 200 + i % 196] = src[i];
    __syncthreads();

    int nu = nch * 50;
    if (tid < nu) {
        int ol = tid / 10, yo = tid % 10;
        int o = c0 * 5 + ol;
        int cil = ol / 5;
        const float* wp = w + o * 25;
        float bb = __ldg(bias + o);
        float acc[10];
#pragma unroll
        for (int t = 0; t < 10; t++) acc[t] = bb;
        for (int ky = 0; ky < 5; ky++) {
            int rb = cil * 200 + (yo + ky) * 14;
            float r[14];
#pragma unroll
            for (int t = 0; t < 14; t++) r[t] = s[rb + t];
#pragma unroll
            for (int kx = 0; kx < 5; kx++) {
                float ww = __ldg(wp + ky * 5 + kx);
#pragma unroll
                for (int xo = 0; xo < 10; xo++)
                    acc[xo] = fmaf(r[xo + kx], ww, acc[xo]);
            }
        }
        float* dst = g_buf3p + b * 26000 + (yo >> 1) * 5200 + o * 20 +
                     (yo & 1) * 10;
#pragma unroll
        for (int t = 0; t < 10; t++) dst[t] = acc[t];
    }
}

// ---------------------------------------------------------------------------
// pc2 + relu + pool:
//   out[g] = dot51(w[g], x[k-block]) + w[g,j]*(x[rep] - x[base+j])
// Thread = (quad, pooled px). Block = (b, py, third). Inputs in 20KB smem;
// weights read directly from L1-resident g_w2pad via __ldg.
// ---------------------------------------------------------------------------
__global__ __launch_bounds__(256, 4)
void pc2pool_kernel(const float* __restrict__ bias) {
    __shared__ float s_in[5120];     // 256 ch x 20
    int bid = blockIdx.x;
    int b = bid / 15;
    int t = bid % 15;
    int py = t / 3, part = t % 3;
    int q0 = part * 44;
    int nq = (part == 2) ? 43 : 44;
    int tid = threadIdx.x;

    {
        float4* si4 = (float4*)s_in;
        const float4* g4 = (const float4*)(g_buf3p + b * 26000 + py * 5200);
        for (int i = tid; i < 1280; i += 256) si4[i] = g4[i];
    }
    __syncthreads();

    int u = tid;
    if (u < nq * 5) {
        int ql = u / 5, px = u % 5;
        int slot0 = (q0 + ql) * 4;
        int base = g_g2sorted[slot0].w;
        const float4* wg = (const float4*)g_w2pad + slot0 * 13;
        float a[4][4];
#pragma unroll
        for (int s2 = 0; s2 < 4; s2++)
#pragma unroll
            for (int p = 0; p < 4; p++) a[s2][p] = 0.f;
        int xb = base * 20 + 2 * px;
#pragma unroll 2
        for (int cc4 = 0; cc4 < 13; cc4++) {
            float4 w0 = __ldg(wg + cc4);
            float4 w1 = __ldg(wg + 13 + cc4);
            float4 w2 = __ldg(wg + 26 + cc4);
            float4 w3 = __ldg(wg + 39 + cc4);
            float w0a[4] = {w0.x, w0.y, w0.z, w0.w};
            float w1a[4] = {w1.x, w1.y, w1.z, w1.w};
            float w2a[4] = {w2.x, w2.y, w2.z, w2.w};
            float w3a[4] = {w3.x, w3.y, w3.z, w3.w};
#pragma unroll
            for (int t2 = 0; t2 < 4; t2++) {
                int c = cc4 * 4 + t2;
                float2 top = *(const float2*)&s_in[xb + c * 20];
                float2 bot = *(const float2*)&s_in[xb + c * 20 + 10];
                a[0][0] = fmaf(w0a[t2], top.x, a[0][0]);
                a[0][1] = fmaf(w0a[t2], top.y, a[0][1]);
                a[0][2] = fmaf(w0a[t2], bot.x, a[0][2]);
                a[0][3] = fmaf(w0a[t2], bot.y, a[0][3]);
                a[1][0] = fmaf(w1a[t2], top.x, a[1][0]);
                a[1][1] = fmaf(w1a[t2], top.y, a[1][1]);
                a[1][2] = fmaf(w1a[t2], bot.x, a[1][2]);
                a[1][3] = fmaf(w1a[t2], bot.y, a[1][3]);
                a[2][0] = fmaf(w2a[t2], top.x, a[2][0]);
                a[2][1] = fmaf(w2a[t2], top.y, a[2][1]);
                a[2][2] = fmaf(w2a[t2], bot.x, a[2][2]);
                a[2][3] = fmaf(w2a[t2], bot.y, a[2][3]);
                a[3][0] = fmaf(w3a[t2], top.x, a[3][0]);
                a[3][1] = fmaf(w3a[t2], top.y, a[3][1]);
                a[3][2] = fmaf(w3a[t2], bot.x, a[3][2]);
                a[3][3] = fmaf(w3a[t2], bot.y, a[3][3]);
            }
        }
#pragma unroll
        for (int s2 = 0; s2 < 4; s2++) {
            int4 gi = g_g2sorted[slot0 + s2];
            float wj = __ldg(&g_w2pad[(slot0 + s2) * 52 + gi.y]);
            int rb2 = gi.z * 20 + 2 * px;
            int bb2 = (base + gi.y) * 20 + 2 * px;
            float2 rt = *(const float2*)&s_in[rb2];
            float2 rb_ = *(const float2*)&s_in[rb2 + 10];
            float2 bt = *(const float2*)&s_in[bb2];
            float2 bb_ = *(const float2*)&s_in[bb2 + 10];
            float v0 = fmaf(wj, rt.x - bt.x, a[s2][0]);
            float v1 = fmaf(wj, rt.y - bt.y, a[s2][1]);
            float v2 = fmaf(wj, rb_.x - bb_.x, a[s2][2]);
            float v3 = fmaf(wj, rb_.y - bb_.y, a[s2][3]);
            float m = fmaxf(fmaxf(v0, v1), fmaxf(v2, v3)) + __ldg(bias + gi.x);
            g_buf4t[b * 13100 + (py * 5 + px) * 524 + gi.x] = fmaxf(m, 0.f);
        }
    }
}

// ---------------------------------------------------------------------------
// oo quarter-K: 1x1 conv 515->100 partials, RED.ADD into bias-seeded g_buf5.
// Block = (b, K-quarter, oc-half) -> grid 512 x 128 threads.
// BOTH x slice (13.2KB) and weight slice (26.4KB) staged to smem -> the
// inner loop is all-LDS (w: lanes consecutive float2, conflict-free;
// x: broadcast float4). Thread = 2 oc x 5 px. Relu happens in fc1.
// ---------------------------------------------------------------------------
__global__ __launch_bounds__(128)
void oo_kernel() {
    __shared__ float xs[25 * 132];   // 13.2 KB
    __shared__ float ws[132 * 50];   // 26.4 KB  [cc][25 float2]
    int u = blockIdx.x;
    int b = u >> 3;
    int r = u & 7;
    int kq = r >> 1, oh = r & 1;
    int c0 = kq * 132;
    int nch = (kq == 3) ? 128 : 132;
    int nf4 = nch >> 2;              // 33 or 32
    int tid = threadIdx.x;

    {   // stage x: 25 rows x nf4 float4
        const float* src = g_buf4t + b * 13100 + c0;
        int n = 25 * nf4;
        for (int i = tid; i < n; i += 128) {
            int row = i / nf4, col = (i % nf4) * 4;
            *(float4*)&xs[row * 132 + col] =
                *(const float4*)(src + row * 524 + col);
        }
    }
    {   // stage w: nch channels x 25 oc-pair float2 (this oh half)
        const float2* wsrc = (const float2*)g_oowT + oh * 25;
        float2* wd = (float2*)ws;
        int nw = nch * 25;
        for (int i = tid; i < nw; i += 128) {
            int cc = i / 25, lo = i % 25;
            wd[cc * 25 + lo] = wsrc[(c0 + cc) * 52 + lo];
        }
    }
    __syncthreads();

    if (tid < 125) {
        int pxg = tid / 25;              // 0..4
        int lo = tid - pxg * 25;         // 0..24
        int oc = (oh * 25 + lo) * 2;
        const float2* w2 = (const float2*)ws + lo;
        const float* x0 = xs + pxg * 5 * 132;
        float a0[5] = {0.f, 0.f, 0.f, 0.f, 0.f};
        float a1[5] = {0.f, 0.f, 0.f, 0.f, 0.f};
        for (int cc = 0; cc < nch; cc += 4) {
            float2 w0 = w2[(cc + 0) * 25];
            float2 w1 = w2[(cc + 1) * 25];
            float2 wq = w2[(cc + 2) * 25];
            float2 w3 = w2[(cc + 3) * 25];
#pragma unroll
            for (int p = 0; p < 5; p++) {
                float4 xv = *(const float4*)&x0[p * 132 + cc];
                a0[p] = fmaf(w0.x, xv.x, a0[p]);
                a1[p] = fmaf(w0.y, xv.x, a1[p]);
                a0[p] = fmaf(w1.x, xv.y, a0[p]);
                a1[p] = fmaf(w1.y, xv.y, a1[p]);
                a0[p] = fmaf(wq.x, xv.z, a0[p]);
                a1[p] = fmaf(wq.y, xv.z, a1[p]);
                a0[p] = fmaf(w3.x, xv.w, a0[p]);
                a1[p] = fmaf(w3.y, xv.w, a1[p]);
            }
        }
        float* dst = g_buf5 + b * 2500;
#pragma unroll
        for (int p = 0; p < 5; p++) {
            int pix = pxg * 5 + p;
            atomicAdd(&dst[oc * 25 + pix], a0[p]);
            atomicAdd(&dst[(oc + 1) * 25 + pix], a1[p]);
        }
    }
}

// ---------------------------------------------------------------------------
// fc1: x = relu(p) on load; [64,2500] x [120,2500]^T + bias, relu.
// Warp tile = 4 outputs x 4 batch.
// ---------------------------------------------------------------------------
__global__ void fc1_kernel(const float* __restrict__ w,
                           const float* __restrict__ bias) {
    int wid = (blockIdx.x * blockDim.x + threadIdx.x) >> 5;
    int lane = threadIdx.x & 31;
    if (wid >= 480) return;
    int o0 = (wid / 16) * 4;
    int b0 = (wid % 16) * 4;
    const float4* w4 = (const float4*)w;
    const float4* x4 = (const float4*)g_buf5;
    float a[16];
#pragma unroll
    for (int t = 0; t < 16; t++) a[t] = 0.f;
    for (int i = lane; i < 625; i += 32) {
        float4 wv[4], xv[4];
#pragma unroll
        for (int t = 0; t < 4; t++) wv[t] = __ldg(w4 + (o0 + t) * 625 + i);
#pragma unroll
        for (int t = 0; t < 4; t++) {
            float4 p = x4[(b0 + t) * 625 + i];
            xv[t].x = fmaxf(p.x, 0.f);
            xv[t].y = fmaxf(p.y, 0.f);
            xv[t].z = fmaxf(p.z, 0.f);
            xv[t].w = fmaxf(p.w, 0.f);
        }
#pragma unroll
        for (int oi = 0; oi < 4; oi++)
#pragma unroll
            for (int bi = 0; bi < 4; bi++) {
                a[oi * 4 + bi] = fmaf(wv[oi].x, xv[bi].x, a[oi * 4 + bi]);
                a[oi * 4 + bi] = fmaf(wv[oi].y, xv[bi].y, a[oi * 4 + bi]);
                a[oi * 4 + bi] = fmaf(wv[oi].z, xv[bi].z, a[oi * 4 + bi]);
                a[oi * 4 + bi] = fmaf(wv[oi].w, xv[bi].w, a[oi * 4 + bi]);
            }
    }
#pragma unroll
    for (int off = 16; off; off >>= 1)
#pragma unroll
        for (int t = 0; t < 16; t++)
            a[t] += __shfl_xor_sync(0xffffffffu, a[t], off);
    if (lane < 16) {
        int oi = lane >> 2, bi = lane & 3;
        g_buf6[(b0 + bi) * 120 + o0 + oi] =
            fmaxf(a[lane] + __ldg(bias + o0 + oi), 0.f);
    }
}

// ---------------------------------------------------------------------------
// fc2 (relu) + fc3 fused. block per batch element.
// ---------------------------------------------------------------------------
__global__ void fc_tail_kernel(const float* __restrict__ w2,
                               const float* __restrict__ b2,
                               const float* __restrict__ w3,
                               const float* __restrict__ b3,
                               float* __restrict__ out) {
    __shared__ float h1[120];
    __shared__ float h2[84];
    int b = blockIdx.x;
    int t = threadIdx.x;
    if (t < 120) h1[t] = g_buf6[b * 120 + t];
    __syncthreads();
    if (t < 84) {
        float acc = __ldg(b2 + t);
        const float* wr = w2 + t * 120;
#pragma unroll 4
        for (int c = 0; c < 120; c++) acc = fmaf(__ldg(wr + c), h1[c], acc);
        h2[t] = fmaxf(acc, 0.0f);
    }
    __syncthreads();
    if (t < 10) {
        float acc = __ldg(b3 + t);
        const float* wr = w3 + t * 84;
#pragma unroll 4
        for (int c = 0; c < 84; c++) acc = fmaf(__ldg(wr + c), h2[c], acc);
        out[b * 10 + t] = acc;
    }
}

// ---------------------------------------------------------------------------
extern "C" void kernel_launch(void* const* d_in, const int* in_sizes, int n_in,
                              void* d_out, int out_size) {
    const float* x     = (const float*)d_in[0];
    const float* dw1_w = (const float*)d_in[1];
    const float* dw1_b = (const float*)d_in[2];
    const float* pc1_w = (const float*)d_in[3];
    const float* pc1_b = (const float*)d_in[4];
    const float* dw2_w = (const float*)d_in[5];
    const float* dw2_b = (const float*)d_in[6];
    const float* pc2_w = (const float*)d_in[7];
    const float* pc2_b = (const float*)d_in[8];
    const float* oo_w  = (const float*)d_in[9];
    const float* oo_b  = (const float*)d_in[10];
    const float* fc1_w = (const float*)d_in[11];
    const float* fc1_b = (const float*)d_in[12];
    const float* fc2_w = (const float*)d_in[13];
    const float* fc2_b = (const float*)d_in[14];
    const float* fc3_w = (const float*)d_in[15];
    const float* fc3_b = (const float*)d_in[16];
    float* out = (float*)d_out;

    front_kernel<<<512, 256>>>(x, dw1_w, dw1_b, pc1_w, pc1_b,
                               pc2_w, oo_w, oo_b);

    dw2_kernel<<<BATCH * 13, 256>>>(dw2_w, dw2_b);

    pc2pool_kernel<<<BATCH * 15, 256>>>(pc2_b);

    oo_kernel<<<512, 128>>>();

    fc1_kernel<<<120, 128>>>(fc1_w, fc1_b);

    fc_tail_kernel<<<BATCH, 128>>>(fc2_w, fc2_b, fc3_w, fc3_b, out);
}